// round 15
// baseline (speedup 1.0000x reference)
#include <cuda_runtime.h>
#include <cstdint>

// Pink noise: 6-pole diagonal IIR + 1-sample delay.
// white[B, L] -> pink[B, L], L=65536.
//
// v12 = v11 + shared power tables: warp 0 computes the lane/wid-indexed
// pole-power tables (m=a^48, m^lane, (m^32)^wid) into smem once per block,
// hidden under the cp.async staging wait; all threads read them with two
// conflict-free LDS.128 + broadcast LDS. Removes ~130 redundant alu ops
// per thread (~9% of total issued instructions).
// Structure unchanged from v11: 4 independent blocks per channel, each with
// an 8192-sample halo warm-up (zeros before channel start), chunk=48,
// stride-52 tile, 3-pole exact scan, fast poles via 2-term neighbor approx.

#define NT      512
#define SEG     16384
#define HALO    8192
#define REGION  (SEG + HALO)            // 24576 samples
#define NW      16
#define RWORDS  52                      // 48 data + 4 pad words per row
#define TILE_FLOATS (NT * RWORDS)       // 26624 floats = 106496 B
#define LROW    65536

typedef unsigned long long ull;

__device__ __forceinline__ ull pk2(float lo, float hi) {
    ull r; asm("mov.b64 %0, {%1, %2};" : "=l"(r) : "f"(lo), "f"(hi)); return r;
}
__device__ __forceinline__ void upk2(ull v, float& lo, float& hi) {
    asm("mov.b64 {%0, %1}, %2;" : "=f"(lo), "=f"(hi) : "l"(v));
}
__device__ __forceinline__ ull ffma2(ull a, ull b, ull c) {
    ull d; asm("fma.rn.f32x2 %0, %1, %2, %3;" : "=l"(d) : "l"(a), "l"(b), "l"(c)); return d;
}
__device__ __forceinline__ ull fmul2(ull a, ull b) {
    ull d; asm("mul.rn.f32x2 %0, %1, %2;" : "=l"(d) : "l"(a), "l"(b)); return d;
}

__device__ __forceinline__ void cpasync16(uint32_t dst, const void* src) {
    asm volatile("cp.async.cg.shared.global [%0], [%1], 16;" :: "r"(dst), "l"(src));
}
#define CP_COMMIT() asm volatile("cp.async.commit_group;" ::: "memory")
#define CP_WAIT0()  asm volatile("cp.async.wait_group 0;" ::: "memory")

__global__ void __launch_bounds__(NT, 2)
pink_kernel(const float* __restrict__ white, float* __restrict__ out) {
    extern __shared__ float tile[];               // TILE_FLOATS
    __shared__ float warpT[NW][3];
    __shared__ float warpW[NW][3];
    __shared__ float fT31[NW][3];
    __shared__ float fT30[NW][3];
    __shared__ float lastw[NW];
    __shared__ float mlaneTab[32][4];             // m_i^lane (i=0..2), pad
    __shared__ float m32wTab[16][4];              // (m_i^32)^wid (i=0..2), pad
    __shared__ float mTab[8];                     // a_i^48 (i=0..5), pad

    const float A0 = 0.99886f, A1 = 0.99332f, A2 = 0.969f,
                A3 = 0.8665f,  A4 = 0.55f,    A5 = -0.7616f;
    const float OC0 = 0.11f * 0.0555179f, OC1 = 0.11f * 0.0750759f,
                OC2 = 0.11f * 0.153852f,  OC3 = 0.11f * 0.3104856f,
                OC4 = 0.11f * 0.5329522f, OC5 = 0.11f * -0.016898f;
    const float OB6 = 0.11f * 0.115926f, ODIR = 0.11f * 0.5362f;

    const int tid  = threadIdx.x;
    const int lane = tid & 31;
    const int wid  = tid >> 5;
    const int ch   = blockIdx.x >> 2;             // channel
    const int sg   = blockIdx.x & 3;              // segment within channel

    // Region start (may be "before" channel start for sg=0; never deref'd there).
    const float* wbase = white + (size_t)ch * LROW + (size_t)sg * SEG - HALO;
    float*       obase = out   + (size_t)ch * LROW + (size_t)sg * SEG;

    // ---------------- Stage the 24576-sample region (one shot) ----------------
    uint32_t tb = (uint32_t)__cvta_generic_to_shared(tile);
    if (sg == 0) {
#pragma unroll
        for (int r = 0; r < 12; r++) {
            int f = tid + r * NT;                 // float4 index [0, 6144)
            int j = f / 12, i = f % 12;
            if (f < HALO / 4) {                   // before channel start -> zeros
                *reinterpret_cast<float4*>(tile + j * RWORDS + i * 4) =
                    make_float4(0.f, 0.f, 0.f, 0.f);
            } else {
                cpasync16(tb + (uint32_t)(j * RWORDS + i * 4) * 4u,
                          wbase + (size_t)f * 4);
            }
        }
    } else {
#pragma unroll
        for (int r = 0; r < 12; r++) {
            int f = tid + r * NT;
            int j = f / 12, i = f % 12;
            cpasync16(tb + (uint32_t)(j * RWORDS + i * 4) * 4u,
                      wbase + (size_t)f * 4);
        }
    }
    CP_COMMIT();

    const ull A01 = pk2(A0, A1), A23 = pk2(A2, A3), A45 = pk2(A4, A5);
    const ull C01 = pk2(OC0, OC1), C23 = pk2(OC2, OC3), C45 = pk2(OC4, OC5);
    const ull ODB = pk2(ODIR, OB6);

    // ---------------- Power tables: computed by warp 0 ONLY (hidden under
    // the staging wait), published via B0 barrier. --------------------------
    if (wid == 0) {
        const float a3v[3] = {A0, A1, A2};
#pragma unroll
        for (int i = 0; i < 3; i++) {
            float t = a3v[i];
            t *= t; t *= t; t *= t; t *= t;       // a^16
            float mi = t * t * t;                  // a^48
            // m^lane
            float b = mi, r = 1.f; int e = lane;
#pragma unroll
            for (int s = 0; s < 5; s++) { if (e & 1) r *= b; b *= b; e >>= 1; }
            mlaneTab[lane][i] = r;                 // b == m^32 now
            // (m^32)^lane for lane<16
            float b2 = b, r2 = 1.f; int e2 = lane;
#pragma unroll
            for (int s = 0; s < 4; s++) { if (e2 & 1) r2 *= b2; b2 *= b2; e2 >>= 1; }
            if (lane < 16) m32wTab[lane][i] = r2;
        }
        if (lane < 6) {
            const float aa[6] = {A0, A1, A2, A3, A4, A5};
            float t = aa[lane];
            t *= t; t *= t; t *= t; t *= t;        // a^16
            mTab[lane] = t * t * t;                // a^48
        }
    }

    CP_WAIT0();
    __syncthreads();                              // B0: region + tables visible

    // Fetch tables (2 conflict-free LDS.128 + broadcast scalar LDS).
    float4 mlv  = *reinterpret_cast<const float4*>(&mlaneTab[lane][0]);
    float4 m32v = *reinterpret_cast<const float4*>(&m32wTab[wid][0]);
    const float m0 = mTab[0], m1 = mTab[1], m2 = mTab[2];
    const float m3 = mTab[3], m4 = mTab[4], m5 = mTab[5];

    const float* wr = tile + tid * RWORDS;        // this thread's 48-sample row

    // ---------------- Pass A: chunk particular state (zero init) ----------------
    float T[6] = {0.f, 0.f, 0.f, 0.f, 0.f, 0.f};
    float w47 = 0.f;
    // sg==0: threads fully inside the zero halo (t*48+47 < 8192 <=> t<=169) skip.
    if (!(sg == 0 && tid <= 169)) {
        ull U01 = 0ull, U23 = 0ull, U45 = 0ull;
#pragma unroll
        for (int q = 0; q < 12; q++) {
            float4 wv = *reinterpret_cast<const float4*>(wr + 4 * q);
            float ws[4] = {wv.x, wv.y, wv.z, wv.w};
#pragma unroll
            for (int c = 0; c < 4; c++) {
                ull W = pk2(ws[c], ws[c]);
                U01 = ffma2(A01, U01, W);
                U23 = ffma2(A23, U23, W);
                U45 = ffma2(A45, U45, W);
            }
            if (q == 11) w47 = wv.w;
        }
        upk2(U01, T[0], T[1]); upk2(U23, T[2], T[3]); upk2(U45, T[4], T[5]);
    }

    // ---------------- Scan: poles 0-2 exact ----------------
    float p0 = T[0], p1 = T[1], p2 = T[2];
    float q0 = m0, q1 = m1, q2 = m2;
#pragma unroll
    for (int o = 1; o < 32; o <<= 1) {
        float u0 = __shfl_up_sync(0xffffffffu, p0, o);
        float u1 = __shfl_up_sync(0xffffffffu, p1, o);
        float u2 = __shfl_up_sync(0xffffffffu, p2, o);
        if (lane >= o) {
            p0 = fmaf(q0, u0, p0);
            p1 = fmaf(q1, u1, p1);
            p2 = fmaf(q2, u2, p2);
        }
        q0 *= q0; q1 *= q1; q2 *= q2;
    }
    // q_i == m_i^32 now
    float ex0 = __shfl_up_sync(0xffffffffu, p0, 1);
    float ex1 = __shfl_up_sync(0xffffffffu, p1, 1);
    float ex2 = __shfl_up_sync(0xffffffffu, p2, 1);
    if (lane == 0) { ex0 = 0.f; ex1 = 0.f; ex2 = 0.f; }

    if (lane == 31) {
        warpT[wid][0] = p0; warpT[wid][1] = p1; warpT[wid][2] = p2;
        fT31[wid][0] = T[3]; fT31[wid][1] = T[4]; fT31[wid][2] = T[5];
        lastw[wid] = w47;
    }
    if (lane == 30) {
        fT30[wid][0] = T[3]; fT30[wid][1] = T[4]; fT30[wid][2] = T[5];
    }
    __syncthreads();                              // B1

    if (wid == 0) {                               // wid0-only combine, 3 poles
        float t0 = (lane < NW) ? warpT[lane][0] : 0.f;
        float t1 = (lane < NW) ? warpT[lane][1] : 0.f;
        float t2 = (lane < NW) ? warpT[lane][2] : 0.f;
        float c0 = q0, c1 = q1, c2 = q2;
#pragma unroll
        for (int o = 1; o < NW; o <<= 1) {
            float u0 = __shfl_up_sync(0xffffffffu, t0, o);
            float u1 = __shfl_up_sync(0xffffffffu, t1, o);
            float u2 = __shfl_up_sync(0xffffffffu, t2, o);
            if (lane >= o) {
                t0 = fmaf(c0, u0, t0);
                t1 = fmaf(c1, u1, t1);
                t2 = fmaf(c2, u2, t2);
            }
            c0 *= c0; c1 *= c1; c2 *= c2;
        }
        if (lane < NW) {
            warpW[lane][0] = t0; warpW[lane][1] = t1; warpW[lane][2] = t2;
        }
    }
    __syncthreads();                              // B2

    // Entry states. Poles 0-2 exact (entry of chunk 0 is 0 - halo absorbs it):
    float E[6];
    {
        float pw0 = (wid == 0) ? 0.f : warpW[wid - 1][0];
        float pw1 = (wid == 0) ? 0.f : warpW[wid - 1][1];
        float pw2 = (wid == 0) ? 0.f : warpW[wid - 1][2];
        E[0] = fmaf(mlv.x, pw0, ex0);
        E[1] = fmaf(mlv.y, pw1, ex1);
        E[2] = fmaf(mlv.z, pw2, ex2);
        // note: m32w tables are folded into warpW combine entry? No — E uses
        // only the previous-warp prefix; the (m^32)^wid factor is not needed
        // because warpW is already the inclusive prefix over warps. (Same as
        // v11, which applied m32w only to segState — absent here.)
        (void)m32v;
    }
    // Poles 3-5: E = T[j-1] + m*T[j-2]  (m3=1.0e-3, m4~3e-13, m5=2.1e-6).
    {
        const float mf[3] = {m3, m4, m5};
#pragma unroll
        for (int k = 0; k < 3; k++) {
            float t = T[3 + k];
            float u1 = __shfl_up_sync(0xffffffffu, t, 1);
            float u2 = __shfl_up_sync(0xffffffffu, t, 2);
            float s1 = (lane > 0) ? u1 : (wid > 0 ? fT31[wid - 1][k] : 0.f);
            float s2;
            if (lane > 1)       s2 = u2;
            else if (lane == 1) s2 = (wid > 0 ? fT31[wid - 1][k] : 0.f);
            else                s2 = (wid > 0 ? fT30[wid - 1][k] : 0.f);
            E[3 + k] = fmaf(mf[k], s2, s1);
        }
    }

    // b6 delayed-white at chunk boundary.
    float pwu = __shfl_up_sync(0xffffffffu, w47, 1);
    float prev_w;
    if (lane > 0)      prev_w = pwu;
    else if (wid > 0)  prev_w = lastw[wid - 1];
    else               prev_w = 0.f;

    // ---------------- Pass B: recompute from E, in-place (output threads only) --
    if (tid >= 170) {                             // chunks overlapping [8192, 24576)
        ull U01 = pk2(E[0], E[1]), U23 = pk2(E[2], E[3]), U45 = pk2(E[4], E[5]);
        float* wrb = tile + tid * RWORDS;
#pragma unroll
        for (int q = 0; q < 12; q++) {
            float4 wv = *reinterpret_cast<const float4*>(wrb + 4 * q);
            float ws[4] = {wv.x, wv.y, wv.z, wv.w};
            float o4[4];
#pragma unroll
            for (int c = 0; c < 4; c++) {
                float w = ws[c];
                ull W = pk2(w, w);
                U01 = ffma2(A01, U01, W);
                U23 = ffma2(A23, U23, W);
                U45 = ffma2(A45, U45, W);
                ull P = ffma2(C01, U01, ffma2(C23, U23, fmul2(C45, U45)));
                ull T2 = ffma2(ODB, pk2(w, prev_w), P);
                float tlo, thi; upk2(T2, tlo, thi);
                o4[c] = tlo + thi;
                prev_w = w;
            }
            *reinterpret_cast<float4*>(wrb + 4 * q) =
                make_float4(o4[0], o4[1], o4[2], o4[3]);
        }
    }
    __syncthreads();                              // B3: outputs in tile

    // ---------------- Coalesced writeout: region offsets [8192, 24576) ----------
#pragma unroll
    for (int r = 0; r < 8; r++) {
        int f = 2048 + tid + r * NT;              // float4 index in region
        int j = f / 12, i = f % 12;
        float4 v = *reinterpret_cast<const float4*>(tile + j * RWORDS + i * 4);
        *reinterpret_cast<float4*>(obase + (size_t)(f - 2048) * 4) = v;
    }
}

extern "C" void kernel_launch(void* const* d_in, const int* in_sizes, int n_in,
                              void* d_out, int out_size) {
    const float* white = (const float*)d_in[0];
    float* out = (float*)d_out;
    int B = out_size / LROW;

    size_t smem = (size_t)TILE_FLOATS * sizeof(float);   // 106496 bytes
    cudaFuncSetAttribute(pink_kernel, cudaFuncAttributeMaxDynamicSharedMemorySize,
                         (int)smem);
    pink_kernel<<<B * 4, NT, smem>>>(white, out);
}